// round 12
// baseline (speedup 1.0000x reference)
#include <cuda_runtime.h>

#define LEVEL 256
#define NBLK  8
#define HH    1024
#define WW    1024
#define TV    640.0f       // (128*128)/LEVEL*THRESH
#define TSTR  17           // table stride in words (17 invertible mod 32)

// per-block uint8 mapping tables (B=16, 64 blocks, 256 bins)
__device__ unsigned char g_maps8[16 * 64 * LEVEL];
// per-image producer counters + consumer counters (self-resetting each launch)
__device__ unsigned int  g_done[16];
__device__ unsigned int  g_cons[16];

// ============================================================================
// Fused kernel. bid < 1024: hist role (64 CTAs per image, image-major).
// bid >= 1024: apply role; spins on g_done[b]==64, then self-resets flags
// once all 256 apply CTAs of the image have passed (net-zero state/launch).
// 256 threads; 17.4KB shared union + <=32 regs -> 8 CTAs/SM.
// ============================================================================
__global__ __launch_bounds__(256, 8) void fused_kernel(const float* __restrict__ img,
                                                       float* __restrict__ out) {
    __shared__ union {
        struct { unsigned int h8[8][LEVEL]; float cs[LEVEL]; int wsum[8]; } h; // ~9KB
        unsigned int tbl[LEVEL * TSTR];                                        // 17.4KB
    } u;

    const int bid = blockIdx.x;
    const int t   = threadIdx.x;

    if (bid < 1024) {
        // ==================== HIST role ====================
        const int b    = bid >> 6;
        const int blk  = bid & 63;
        const int bi   = blk >> 3, bj = blk & 7;
        const int lane = t & 31, warp = t >> 5;   // 8 warps

        #pragma unroll
        for (int k = 0; k < 8; ++k) ((unsigned int*)u.h.h8)[t + k * 256] = 0u;
        __syncthreads();

        const float* base = img + ((size_t)b * HH + (size_t)bi * 128) * WW + bj * 128;
        unsigned int* hw = u.h.h8[warp];
        #pragma unroll 8
        for (int k = 0; k < 16; ++k) {
            int idx = k * 256 + t;
            int row = idx >> 5;
            int c4  = idx & 31;
            float4 p = *reinterpret_cast<const float4*>(base + (size_t)row * WW + c4 * 4);
            atomicAdd(&hw[(int)p.x], 1u);
            atomicAdd(&hw[(int)p.y], 1u);
            atomicAdd(&hw[(int)p.z], 1u);
            atomicAdd(&hw[(int)p.w], 1u);
        }
        __syncthreads();

        unsigned int s = 0u;
        #pragma unroll
        for (int w = 0; w < 8; ++w) s += u.h.h8[w][t];
        const float h = (float)s;

        // clip: redistribute excess above TV uniformly
        int eloc = (int)fmaxf(h - TV, 0.f);
        #pragma unroll
        for (int off = 16; off; off >>= 1)
            eloc += __shfl_xor_sync(0xffffffffu, eloc, off);
        if (lane == 0) u.h.wsum[warp] = eloc;
        __syncthreads();
        int tot = 0;
        #pragma unroll
        for (int w = 0; w < 8; ++w) tot += u.h.wsum[w];
        const float me = (float)tot * (1.0f / 256.0f);
        u.h.cs[t] = floorf((h >= TV) ? (TV + me) : (h + me));
        __syncthreads();

        // inclusive scan over 256 bins (warp 0)
        if (warp == 0) {
            float run = 0.f;
            #pragma unroll
            for (int ch = 0; ch < 8; ++ch) {
                float v = u.h.cs[ch * 32 + lane];
                #pragma unroll
                for (int off = 1; off < 32; off <<= 1) {
                    float n = __shfl_up_sync(0xffffffffu, v, off);
                    if (lane >= off) v += n;
                }
                v += run;
                u.h.cs[ch * 32 + lane] = v;
                run = __shfl_sync(0xffffffffu, v, 31);
            }
        }
        __syncthreads();

        if (t < 64) {
            unsigned char* gm = g_maps8 + (size_t)(b * 64 + blk) * LEVEL;
            uchar4 q;
            q.x = (unsigned char)(((int)floorf(u.h.cs[4 * t + 0] * (255.0f / 16384.0f))) & 255);
            q.y = (unsigned char)(((int)floorf(u.h.cs[4 * t + 1] * (255.0f / 16384.0f))) & 255);
            q.z = (unsigned char)(((int)floorf(u.h.cs[4 * t + 2] * (255.0f / 16384.0f))) & 255);
            q.w = (unsigned char)(((int)floorf(u.h.cs[4 * t + 3] * (255.0f / 16384.0f))) & 255);
            *reinterpret_cast<uchar4*>(gm + 4 * t) = q;
        }
        __threadfence();          // release maps before flag
        __syncthreads();
        if (t == 0) atomicAdd(&g_done[b], 1u);

    } else {
        // ==================== APPLY role ====================
        const int a    = bid - 1024;
        const int b    = a >> 8;
        const int tile = a & 255;
        const int i0   = (tile >> 4) * 64;
        const int j0   = (tile & 15) * 64;
        const int tx   = t & 15, ty = t >> 4;
        const int lane = t & 31;

        // wait for this image's 64 hist CTAs
        if (t == 0) {
            volatile unsigned int* f = &g_done[b];
            while (*f < 64u) __nanosleep(256);
        }
        __syncthreads();          // acquire for whole CTA

        // self-reset: 256th apply CTA of image b zeroes both flags
        if (t == 0) {
            unsigned int old = atomicAdd(&g_cons[b], 1u);
            if (old == 255u) { g_done[b] = 0u; g_cons[b] = 0u; }
        }

        const int r  = (i0 < 64) ? 0 : ((i0 - 64) >> 7);
        const int c  = (j0 < 64) ? 0 : ((j0 - 64) >> 7);
        const int rp = min(r + 1, NBLK - 1);
        const int cp = min(c + 1, NBLK - 1);

        // packed word {lu, lb, ru, rb} for value v = t; 16 copies, stride 17
        {
            const unsigned char* gm = g_maps8 + (size_t)b * 64 * LEVEL;
            unsigned int w = (unsigned int)gm[(r  * 8 + c ) * LEVEL + t]
                           | ((unsigned int)gm[(rp * 8 + c ) * LEVEL + t] << 8)
                           | ((unsigned int)gm[(r  * 8 + cp) * LEVEL + t] << 16)
                           | ((unsigned int)gm[(rp * 8 + cp) * LEVEL + t] << 24);
            #pragma unroll
            for (int k = 0; k < 16; ++k)
                u.tbl[t * TSTR + ((lane + k) & 15)] = w;   // 17t perm mod 32: no conflicts
        }
        __syncthreads();

        const bool xz  = (r >= NBLK - 1);
        const bool yz  = (c >= NBLK - 1);
        const bool ext = (i0 == 0) || (j0 == 0);   // extrapolation band

        const int jbase = j0 + tx * 4;
        float yw[4];
        #pragma unroll
        for (int uu = 0; uu < 4; ++uu)
            yw[uu] = yz ? 0.f : (float)(jbase + uu - c * 128 - 64) * (1.0f / 128.0f);

        const float*        ip  = img + (size_t)b * HH * WW + jbase;
        float*              op  = out + (size_t)b * HH * WW + jbase;
        const unsigned int* sml = u.tbl + (lane & 15);

        // depth-2 software pipeline over the 4 row-groups
        float4 pa = __ldcs(reinterpret_cast<const float4*>(ip + (size_t)(i0 + ty) * WW));
        float4 pb = __ldcs(reinterpret_cast<const float4*>(ip + (size_t)(i0 + ty + 16) * WW));

        #pragma unroll
        for (int k = 0; k < 4; ++k) {
            const int i = i0 + ty + k * 16;
            const float4 p = pa;
            pa = pb;
            if (k < 2)
                pb = __ldcs(reinterpret_cast<const float4*>(ip + (size_t)(i + 32) * WW));

            const float xw = xz ? 0.f : (float)(i - r * 128 - 64) * (1.0f / 128.0f);
            float vals[4] = {p.x, p.y, p.z, p.w};
            float res[4];
            #pragma unroll
            for (int uu = 0; uu < 4; ++uu) {
                const unsigned int m = sml[((int)vals[uu]) * TSTR];  // ~1.4 wf LDS
                // magic floats: value = 32768 + byte (exact)
                const float lu = __uint_as_float(__byte_perm(m, 0x47000000u, 0x7404));
                const float lb = __uint_as_float(__byte_perm(m, 0x47000000u, 0x7414));
                const float ru = __uint_as_float(__byte_perm(m, 0x47000000u, 0x7424));
                const float rb = __uint_as_float(__byte_perm(m, 0x47000000u, 0x7434));
                const float d1 = lb - lu;               // exact (bias cancels)
                const float d2 = rb - ru;
                const float aa = fmaf(xw, d1, lu);      // 32768 + a_true, exact
                const float bb = fmaf(xw, d2, ru);
                const float d3 = bb - aa;               // exact
                const float o  = fmaf(yw[uu], d3, aa - 32768.0f);  // exact bilinear
                res[uu] = ext ? (float)(((int)o) & 255)  // trunc toward 0 + %256
                              : floorf(o);               // o in [0,255] interior
            }
            __stcs(reinterpret_cast<float4*>(op + (size_t)i * WW),
                   make_float4(res[0], res[1], res[2], res[3]));
        }
    }
}

extern "C" void kernel_launch(void* const* d_in, const int* in_sizes, int n_in,
                              void* d_out, int out_size) {
    const float* img = (const float*)d_in[0];
    float*       out = (float*)d_out;
    fused_kernel<<<1024 + 4096, 256>>>(img, out);
}